// round 1
// baseline (speedup 1.0000x reference)
#include <cuda_runtime.h>
#include <cstdint>

#define NMAX 100000
#define H 128

// -------- scratch (device globals; no allocation allowed) --------
__device__ float d_h  [(size_t)NMAX * H];   // node features (layer input)
__device__ float d_h2 [(size_t)NMAX * H];   // h @ W
__device__ float d_agg[(size_t)NMAX * H];   // edge aggregation
__device__ float d_dis[NMAX];               // deg -> rsqrt(deg+1)
__device__ float d_g  [H];                  // column sums for mean pool
__device__ int   d_is64;                    // edge_index is int64?

// -------- edge index width detection --------
__global__ void detect_kernel(const int* ei, int E) {
    if (threadIdx.x == 0 && blockIdx.x == 0) {
        int n = E < 64 ? E : 64;
        int all0 = 1;
        for (int i = 0; i < n; i++)
            if (ei[2 * i + 1] != 0) { all0 = 0; break; }
        d_is64 = all0;  // int64 values < 2^31 -> high words all zero
    }
}

__device__ __forceinline__ int edge_at(const void* ei, long long i) {
    if (d_is64) return (int)((const long long*)ei)[i];
    return ((const int*)ei)[i];
}

// -------- degree (counts into d_dis, which starts zeroed) --------
__global__ void degree_kernel(const void* ei, int E) {
    int e = blockIdx.x * blockDim.x + threadIdx.x;
    if (e < E) {
        int dst = edge_at(ei, (long long)E + e);
        atomicAdd(&d_dis[dst], 1.0f);
    }
}

__global__ void dis_kernel(int N) {
    int i = blockIdx.x * blockDim.x + threadIdx.x;
    if (i < N) d_dis[i] = rsqrtf(d_dis[i] + 1.0f);
}

// -------- embedding: h = x @ emb_w + emb_b  (x: [N,16], W: [16,128]) --------
__global__ void embed_kernel(const float* __restrict__ x,
                             const float* __restrict__ W,
                             const float* __restrict__ b, int N) {
    __shared__ float ws[16][H];
    __shared__ float xs[32][16];
    int tid = threadIdx.x;  // 128
    for (int i = tid; i < 16 * H; i += 128) ws[i / H][i % H] = W[i];
    float bias = b[tid];
    int n0 = blockIdx.x * 32;
    int nodes = min(32, N - n0);
    for (int i = tid; i < nodes * 16; i += 128) xs[i / 16][i % 16] = x[(size_t)n0 * 16 + i];
    __syncthreads();
    for (int n = 0; n < nodes; n++) {
        float s = bias;
#pragma unroll
        for (int k = 0; k < 16; k++) s += xs[n][k] * ws[k][tid];
        d_h[(size_t)(n0 + n) * H + tid] = s;
    }
}

// -------- SGEMM: d_h2 = d_h @ W   (W: [128,128]) --------
// 64-row x 128-col tile, 256 threads, 4x8 micro-tile, K chunks of 32.
#define TM 64
__global__ void gemm_kernel(const float* __restrict__ W, int N) {
    __shared__ float hs[TM][33];
    __shared__ float ws[32][H];
    int row0 = blockIdx.x * TM;
    int tid = threadIdx.x;         // 256
    int tx = tid & 15;             // col group: cols tx*8 .. tx*8+7
    int ty = tid >> 4;             // row group: rows ty*4 .. ty*4+3
    float acc[4][8];
#pragma unroll
    for (int i = 0; i < 4; i++)
#pragma unroll
        for (int j = 0; j < 8; j++) acc[i][j] = 0.0f;

    for (int k0 = 0; k0 < H; k0 += 32) {
        for (int i = tid; i < TM * 32; i += 256) {
            int r = i >> 5, c = i & 31;
            int gr = row0 + r;
            hs[r][c] = (gr < N) ? d_h[(size_t)gr * H + k0 + c] : 0.0f;
        }
        for (int i = tid; i < 32 * H; i += 256) {
            int r = i >> 7, c = i & 127;
            ws[r][c] = W[(size_t)(k0 + r) * H + c];
        }
        __syncthreads();
#pragma unroll
        for (int k = 0; k < 32; k++) {
            float a[4], bb[8];
#pragma unroll
            for (int i = 0; i < 4; i++) a[i] = hs[ty * 4 + i][k];
#pragma unroll
            for (int j = 0; j < 8; j++) bb[j] = ws[k][tx * 8 + j];
#pragma unroll
            for (int i = 0; i < 4; i++)
#pragma unroll
                for (int j = 0; j < 8; j++) acc[i][j] += a[i] * bb[j];
        }
        __syncthreads();
    }
#pragma unroll
    for (int i = 0; i < 4; i++) {
        int gr = row0 + ty * 4 + i;
        if (gr < N) {
#pragma unroll
            for (int j = 0; j < 8; j++)
                d_h2[(size_t)gr * H + tx * 8 + j] = acc[i][j];
        }
    }
}

// -------- edge scatter: agg[dst] += h2[src] * dis[src]*dis[dst] --------
// One warp per edge; each lane handles a float4 chunk (32 lanes * 4 = 128).
__global__ void scatter_kernel(const void* ei, int E) {
    long long t = (long long)blockIdx.x * blockDim.x + threadIdx.x;
    if (t >= (long long)E * 32) return;
    int e = (int)(t >> 5);
    int c = (int)(t & 31);
    int src, dst;
    if (d_is64) {
        const long long* p = (const long long*)ei;
        src = (int)p[e];
        dst = (int)p[(long long)E + e];
    } else {
        const int* p = (const int*)ei;
        src = p[e];
        dst = p[E + e];
    }
    float coef = d_dis[src] * d_dis[dst];
    float4 v = *(const float4*)&d_h2[(size_t)src * H + c * 4];
    float4 m = make_float4(v.x * coef, v.y * coef, v.z * coef, v.w * coef);
    float* addr = &d_agg[(size_t)dst * H + c * 4];
    asm volatile("red.global.add.v4.f32 [%0], {%1,%2,%3,%4};"
                 :: "l"(addr), "f"(m.x), "f"(m.y), "f"(m.z), "f"(m.w)
                 : "memory");
}

// -------- combine: h = relu(agg + h2*dis^2 + b); re-zero agg for next layer --------
__global__ void combine_kernel(const float* __restrict__ b, int N) {
    long long i = (long long)blockIdx.x * blockDim.x + threadIdx.x;
    if (i < (long long)N * H) {
        int node = (int)(i >> 7);
        int col = (int)(i & 127);
        float dis = d_dis[node];
        float v = d_agg[i] + d_h2[i] * (dis * dis) + b[col];
        d_h[i] = fmaxf(v, 0.0f);
        d_agg[i] = 0.0f;
    }
}

// -------- global mean pool: column sums into d_g --------
__global__ void colsum_kernel(int N) {
    int col = threadIdx.x;  // 128
    float s = 0.0f;
    for (int n = blockIdx.x; n < N; n += gridDim.x)
        s += d_h[(size_t)n * H + col];
    atomicAdd(&d_g[col], s);
}

// -------- MLP head: out = relu(mean @ fc1 + b1) @ fc2 + b2 --------
__global__ void head_kernel(const float* __restrict__ fc1w, const float* __restrict__ fc1b,
                            const float* __restrict__ fc2w, const float* __restrict__ fc2b,
                            float* __restrict__ out, int N) {
    __shared__ float sg[H], sg1[H];
    int tid = threadIdx.x;  // 128
    sg[tid] = d_g[tid] / (float)N;
    __syncthreads();
    float s = fc1b[tid];
#pragma unroll 16
    for (int k = 0; k < H; k++) s += sg[k] * fc1w[(size_t)k * H + tid];
    sg1[tid] = fmaxf(s, 0.0f);
    __syncthreads();
    if (tid < 64) {
        float o = fc2b[tid];
#pragma unroll 16
        for (int k = 0; k < H; k++) o += sg1[k] * fc2w[(size_t)k * 64 + tid];
        out[tid] = o;
    }
}

extern "C" void kernel_launch(void* const* d_in, const int* in_sizes, int n_in,
                              void* d_out, int out_size) {
    const float* x      = (const float*)d_in[0];
    const void*  ei     = d_in[1];
    const float* emb_w  = (const float*)d_in[2];
    const float* emb_b  = (const float*)d_in[3];
    const float* conv_w = (const float*)d_in[4];
    const float* conv_b = (const float*)d_in[5];
    const float* fc1_w  = (const float*)d_in[6];
    const float* fc1_b  = (const float*)d_in[7];
    const float* fc2_w  = (const float*)d_in[8];
    const float* fc2_b  = (const float*)d_in[9];
    float* out = (float*)d_out;

    int N = in_sizes[0] / 16;   // 100000
    int E = in_sizes[1] / 2;    // 1600000 (element count same for i32/i64)

    void *agg_p, *dis_p, *g_p;
    cudaGetSymbolAddress(&agg_p, d_agg);
    cudaGetSymbolAddress(&dis_p, d_dis);
    cudaGetSymbolAddress(&g_p, d_g);
    cudaMemsetAsync(agg_p, 0, (size_t)N * H * sizeof(float));
    cudaMemsetAsync(dis_p, 0, (size_t)N * sizeof(float));
    cudaMemsetAsync(g_p, 0, H * sizeof(float));

    detect_kernel<<<1, 32>>>((const int*)ei, E);
    degree_kernel<<<(E + 255) / 256, 256>>>(ei, E);
    dis_kernel<<<(N + 255) / 256, 256>>>(N);
    embed_kernel<<<(N + 31) / 32, 128>>>(x, emb_w, emb_b, N);

    long long stotal = (long long)E * 32;
    int sblocks = (int)((stotal + 255) / 256);
    int cblocks = (int)(((long long)N * H + 255) / 256);

    for (int l = 0; l < 3; l++) {
        gemm_kernel<<<(N + TM - 1) / TM, 256>>>(conv_w + (size_t)l * H * H, N);
        scatter_kernel<<<sblocks, 256>>>(ei, E);
        combine_kernel<<<cblocks, 256>>>(conv_b + (size_t)l * H, N);
    }

    colsum_kernel<<<512, 128>>>(N);
    head_kernel<<<1, 128>>>(fc1_w, fc1_b, fc2_w, fc2_b, out, N);
}

// round 2
// speedup vs baseline: 1.6877x; 1.6877x over previous
#include <cuda_runtime.h>
#include <cstdint>

#define NMAX 100000
#define EMAX 1600000
#define H 128

// -------- scratch (device globals; no allocation allowed) --------
__device__ float d_h  [(size_t)NMAX * H];   // node features (layer input)
__device__ float d_h2 [(size_t)NMAX * H];   // h @ W
__device__ float d_dis[NMAX];               // degree count -> rsqrt(deg+1)
__device__ int   d_rowstart[NMAX + 1];      // CSR row offsets (by dst)
__device__ int   d_cursor[NMAX];            // placement cursors
__device__ int   d_csrc[EMAX];              // CSR src indices
__device__ float d_cscale[EMAX];            // dis[src] per edge
__device__ float d_g[H];                    // column sums for mean pool
__device__ int   d_is64;                    // edge_index is int64?

// -------- edge index width detection --------
__global__ void detect_kernel(const int* ei, int E) {
    if (threadIdx.x == 0 && blockIdx.x == 0) {
        int n = E < 64 ? E : 64;
        int all0 = 1;
        for (int i = 0; i < n; i++)
            if (ei[2 * i + 1] != 0) { all0 = 0; break; }
        d_is64 = all0;  // int64 values < 2^31 -> high words all zero
    }
}

__device__ __forceinline__ void edge_pair(const void* ei, int E, int e, int& src, int& dst) {
    if (d_is64) {
        const long long* p = (const long long*)ei;
        src = (int)p[e];
        dst = (int)p[(long long)E + e];
    } else {
        const int* p = (const int*)ei;
        src = p[e];
        dst = p[E + e];
    }
}

// -------- degree histogram (float counts into d_dis, which starts zeroed) --------
__global__ void degree_kernel(const void* ei, int E) {
    int e = blockIdx.x * blockDim.x + threadIdx.x;
    if (e < E) {
        int src, dst;
        edge_pair(ei, E, e, src, dst);
        atomicAdd(&d_dis[dst], 1.0f);
    }
}

// -------- single-block exclusive scan of degrees -> rowstart & cursor --------
__global__ void scan_kernel(int N, int E) {
    __shared__ float ssum[1024];
    int tid = threadIdx.x;  // 1024
    int C = (N + 1023) / 1024;
    int lo = tid * C, hi = min(lo + C, N);
    float local = 0.0f;
    for (int i = lo; i < hi; i++) local += d_dis[i];
    ssum[tid] = local;
    __syncthreads();
    // Hillis-Steele inclusive scan
    for (int off = 1; off < 1024; off <<= 1) {
        float v = (tid >= off) ? ssum[tid - off] : 0.0f;
        __syncthreads();
        ssum[tid] += v;
        __syncthreads();
    }
    float run = (tid > 0) ? ssum[tid - 1] : 0.0f;  // exclusive prefix
    for (int i = lo; i < hi; i++) {
        int r = (int)run;
        d_rowstart[i] = r;
        d_cursor[i] = r;
        run += d_dis[i];
    }
    if (tid == 0) d_rowstart[N] = E;
}

// -------- dis transform --------
__global__ void dis_kernel(int N) {
    int i = blockIdx.x * blockDim.x + threadIdx.x;
    if (i < N) d_dis[i] = rsqrtf(d_dis[i] + 1.0f);
}

// -------- counting-sort placement into CSR --------
__global__ void place_kernel(const void* ei, int E) {
    int e = blockIdx.x * blockDim.x + threadIdx.x;
    if (e < E) {
        int src, dst;
        edge_pair(ei, E, e, src, dst);
        int pos = atomicAdd(&d_cursor[dst], 1);
        d_csrc[pos] = src;
        d_cscale[pos] = d_dis[src];
    }
}

// -------- embedding: h = x @ emb_w + emb_b  (x: [N,16], W: [16,128]) --------
__global__ void embed_kernel(const float* __restrict__ x,
                             const float* __restrict__ W,
                             const float* __restrict__ b, int N) {
    __shared__ float ws[16][H];
    __shared__ float xs[32][16];
    int tid = threadIdx.x;  // 128
    for (int i = tid; i < 16 * H; i += 128) ws[i / H][i % H] = W[i];
    float bias = b[tid];
    int n0 = blockIdx.x * 32;
    int nodes = min(32, N - n0);
    for (int i = tid; i < nodes * 16; i += 128) xs[i / 16][i % 16] = x[(size_t)n0 * 16 + i];
    __syncthreads();
    for (int n = 0; n < nodes; n++) {
        float s = bias;
#pragma unroll
        for (int k = 0; k < 16; k++) s += xs[n][k] * ws[k][tid];
        d_h[(size_t)(n0 + n) * H + tid] = s;
    }
}

// -------- SGEMM: d_h2 = d_h @ W   (W: [128,128]) --------
// 128x128 tile, 256 threads, 8x8 micro-tile, K chunks of 32.
#define TM 128
__global__ __launch_bounds__(256) void gemm_kernel(const float* __restrict__ W, int N) {
    __shared__ float hs[TM][33];
    __shared__ float ws[32][H];
    int row0 = blockIdx.x * TM;
    int tid = threadIdx.x;         // 256
    int tx = tid & 15;             // col group: cols tx*8 .. tx*8+7
    int ty = tid >> 4;             // row group: rows ty*8 .. ty*8+7
    float acc[8][8];
#pragma unroll
    for (int i = 0; i < 8; i++)
#pragma unroll
        for (int j = 0; j < 8; j++) acc[i][j] = 0.0f;

    for (int k0 = 0; k0 < H; k0 += 32) {
        // load hs: 128 rows x 32 cols = 1024 float4, 4 per thread
#pragma unroll
        for (int v = 0; v < 4; v++) {
            int i = tid + v * 256;        // float4 index
            int r = i >> 3, c4 = (i & 7) * 4;
            int gr = row0 + r;
            float4 val = make_float4(0.f, 0.f, 0.f, 0.f);
            if (gr < N) val = *(const float4*)&d_h[(size_t)gr * H + k0 + c4];
            hs[r][c4 + 0] = val.x; hs[r][c4 + 1] = val.y;
            hs[r][c4 + 2] = val.z; hs[r][c4 + 3] = val.w;
        }
        // load ws: 32 rows x 128 cols = 1024 float4
#pragma unroll
        for (int v = 0; v < 4; v++) {
            int i = tid + v * 256;
            int r = i >> 5, c4 = (i & 31) * 4;
            float4 val = *(const float4*)&W[(size_t)(k0 + r) * H + c4];
            ws[r][c4 + 0] = val.x; ws[r][c4 + 1] = val.y;
            ws[r][c4 + 2] = val.z; ws[r][c4 + 3] = val.w;
        }
        __syncthreads();
#pragma unroll
        for (int k = 0; k < 32; k++) {
            float a[8], bb[8];
#pragma unroll
            for (int i = 0; i < 8; i++) a[i] = hs[ty * 8 + i][k];
#pragma unroll
            for (int j = 0; j < 8; j++) bb[j] = ws[k][tx * 8 + j];
#pragma unroll
            for (int i = 0; i < 8; i++)
#pragma unroll
                for (int j = 0; j < 8; j++) acc[i][j] += a[i] * bb[j];
        }
        __syncthreads();
    }
#pragma unroll
    for (int i = 0; i < 8; i++) {
        int gr = row0 + ty * 8 + i;
        if (gr < N) {
            float4 v0 = make_float4(acc[i][0], acc[i][1], acc[i][2], acc[i][3]);
            float4 v1 = make_float4(acc[i][4], acc[i][5], acc[i][6], acc[i][7]);
            *(float4*)&d_h2[(size_t)gr * H + tx * 8 + 0] = v0;
            *(float4*)&d_h2[(size_t)gr * H + tx * 8 + 4] = v1;
        }
    }
}

// -------- fused gather + combine: one warp per dst node --------
// h[dst] = relu( (sum_e h2[src_e]*dis[src_e]) * dis[dst] + h2[dst]*dis[dst]^2 + b )
__global__ void gather_kernel(const float* __restrict__ b, int N) {
    int w = (blockIdx.x * blockDim.x + threadIdx.x) >> 5;
    if (w >= N) return;
    int lane = threadIdx.x & 31;
    int beg = d_rowstart[w], end = d_rowstart[w + 1];
    float ax = 0.f, ay = 0.f, az = 0.f, aw = 0.f;
    int i = beg;
    for (; i + 2 <= end; i += 2) {
        int s0 = d_csrc[i], s1 = d_csrc[i + 1];
        float c0 = d_cscale[i], c1 = d_cscale[i + 1];
        float4 v0 = *(const float4*)&d_h2[(size_t)s0 * H + lane * 4];
        float4 v1 = *(const float4*)&d_h2[(size_t)s1 * H + lane * 4];
        ax += v0.x * c0; ay += v0.y * c0; az += v0.z * c0; aw += v0.w * c0;
        ax += v1.x * c1; ay += v1.y * c1; az += v1.z * c1; aw += v1.w * c1;
    }
    if (i < end) {
        int s0 = d_csrc[i];
        float c0 = d_cscale[i];
        float4 v0 = *(const float4*)&d_h2[(size_t)s0 * H + lane * 4];
        ax += v0.x * c0; ay += v0.y * c0; az += v0.z * c0; aw += v0.w * c0;
    }
    float dd = d_dis[w];
    float dd2 = dd * dd;
    float4 hv = *(const float4*)&d_h2[(size_t)w * H + lane * 4];
    float4 bb = *(const float4*)&b[lane * 4];
    float4 o;
    o.x = fmaxf(ax * dd + hv.x * dd2 + bb.x, 0.0f);
    o.y = fmaxf(ay * dd + hv.y * dd2 + bb.y, 0.0f);
    o.z = fmaxf(az * dd + hv.z * dd2 + bb.z, 0.0f);
    o.w = fmaxf(aw * dd + hv.w * dd2 + bb.w, 0.0f);
    *(float4*)&d_h[(size_t)w * H + lane * 4] = o;
}

// -------- global mean pool: column sums into d_g --------
__global__ void colsum_kernel(int N) {
    int col = threadIdx.x;  // 128
    float s = 0.0f;
    for (int n = blockIdx.x; n < N; n += gridDim.x)
        s += d_h[(size_t)n * H + col];
    atomicAdd(&d_g[col], s);
}

// -------- MLP head: out = relu(mean @ fc1 + b1) @ fc2 + b2 --------
__global__ void head_kernel(const float* __restrict__ fc1w, const float* __restrict__ fc1b,
                            const float* __restrict__ fc2w, const float* __restrict__ fc2b,
                            float* __restrict__ out, int N) {
    __shared__ float sg[H], sg1[H];
    int tid = threadIdx.x;  // 128
    sg[tid] = d_g[tid] / (float)N;
    __syncthreads();
    float s = fc1b[tid];
#pragma unroll 16
    for (int k = 0; k < H; k++) s += sg[k] * fc1w[(size_t)k * H + tid];
    sg1[tid] = fmaxf(s, 0.0f);
    __syncthreads();
    if (tid < 64) {
        float o = fc2b[tid];
#pragma unroll 16
        for (int k = 0; k < H; k++) o += sg1[k] * fc2w[(size_t)k * 64 + tid];
        out[tid] = o;
    }
}

extern "C" void kernel_launch(void* const* d_in, const int* in_sizes, int n_in,
                              void* d_out, int out_size) {
    const float* x      = (const float*)d_in[0];
    const void*  ei     = d_in[1];
    const float* emb_w  = (const float*)d_in[2];
    const float* emb_b  = (const float*)d_in[3];
    const float* conv_w = (const float*)d_in[4];
    const float* conv_b = (const float*)d_in[5];
    const float* fc1_w  = (const float*)d_in[6];
    const float* fc1_b  = (const float*)d_in[7];
    const float* fc2_w  = (const float*)d_in[8];
    const float* fc2_b  = (const float*)d_in[9];
    float* out = (float*)d_out;

    int N = in_sizes[0] / 16;   // 100000
    int E = in_sizes[1] / 2;    // 1600000

    void *dis_p, *g_p;
    cudaGetSymbolAddress(&dis_p, d_dis);
    cudaGetSymbolAddress(&g_p, d_g);
    cudaMemsetAsync(dis_p, 0, (size_t)N * sizeof(float));
    cudaMemsetAsync(g_p, 0, H * sizeof(float));

    detect_kernel<<<1, 32>>>((const int*)ei, E);
    degree_kernel<<<(E + 255) / 256, 256>>>(ei, E);
    scan_kernel<<<1, 1024>>>(N, E);
    dis_kernel<<<(N + 255) / 256, 256>>>(N);
    place_kernel<<<(E + 255) / 256, 256>>>(ei, E);
    embed_kernel<<<(N + 31) / 32, 128>>>(x, emb_w, emb_b, N);

    int gblocks = (int)(((long long)N * 32 + 255) / 256);

    for (int l = 0; l < 3; l++) {
        gemm_kernel<<<(N + TM - 1) / TM, 256>>>(conv_w + (size_t)l * H * H, N);
        gather_kernel<<<gblocks, 256>>>(conv_b + (size_t)l * H, N);
    }

    colsum_kernel<<<512, 128>>>(N);
    head_kernel<<<1, 128>>>(fc1_w, fc1_b, fc2_w, fc2_b, out, N);
}

// round 4
// speedup vs baseline: 2.2288x; 1.3206x over previous
#include <cuda_runtime.h>
#include <cstdint>

#define NMAX 100000
#define NPAD 100096
#define EMAX 1600000
#define H 128

// -------- scratch (device globals; no allocation allowed) --------
__device__ float    d_h  [(size_t)NPAD * H];   // node features (padded; pad rows stay 0)
__device__ float    d_h2 [(size_t)NPAD * H];   // h @ W
__device__ float    d_dis[NMAX];               // degree count -> rsqrt(deg+1)
__device__ int      d_rowstart[NMAX + 1];      // CSR row offsets (by dst)
__device__ int      d_cursor[NMAX];            // placement cursors
__device__ int      d_csrc[EMAX];              // CSR src indices
__device__ float    d_cscale[EMAX];            // dis[src] per edge
__device__ uint32_t d_wt[3 * H * H];           // fragment-ordered tf32 W images
__device__ float    d_g[H];                    // column sums for mean pool
__device__ int      d_is64;                    // edge_index is int64?

__device__ __forceinline__ uint32_t f2tf(float f) {
    uint32_t u;
    asm("cvt.rna.tf32.f32 %0, %1;" : "=r"(u) : "f"(f));
    return u;
}

#define MMA_TF32(c, a, b0, b1)                                                 \
    asm volatile("mma.sync.aligned.m16n8k8.row.col.f32.tf32.tf32.f32 "         \
        "{%0,%1,%2,%3}, {%4,%5,%6,%7}, {%8,%9}, {%0,%1,%2,%3};"                \
        : "+f"((c)[0]), "+f"((c)[1]), "+f"((c)[2]), "+f"((c)[3])               \
        : "r"((a)[0]), "r"((a)[1]), "r"((a)[2]), "r"((a)[3]),                  \
          "r"(b0), "r"(b1))

// ==================== preprocessing ====================
__global__ void detect_kernel(const int* ei, int E) {
    if (threadIdx.x == 0 && blockIdx.x == 0) {
        int n = E < 64 ? E : 64;
        int all0 = 1;
        for (int i = 0; i < n; i++)
            if (ei[2 * i + 1] != 0) { all0 = 0; break; }
        d_is64 = all0;
    }
}

__device__ __forceinline__ void edge_pair(const void* ei, int E, int e, int& src, int& dst) {
    if (d_is64) {
        const long long* p = (const long long*)ei;
        src = (int)p[e];
        dst = (int)p[(long long)E + e];
    } else {
        const int* p = (const int*)ei;
        src = p[e];
        dst = p[E + e];
    }
}

__global__ void degree_kernel(const void* ei, int E) {
    int e = blockIdx.x * blockDim.x + threadIdx.x;
    if (e < E) {
        int src, dst;
        edge_pair(ei, E, e, src, dst);
        atomicAdd(&d_dis[dst], 1.0f);
    }
}

__global__ void scan_kernel(int N, int E) {
    __shared__ float ssum[1024];
    int tid = threadIdx.x;
    int C = (N + 1023) / 1024;
    int lo = tid * C, hi = min(lo + C, N);
    float local = 0.0f;
    for (int i = lo; i < hi; i++) local += d_dis[i];
    ssum[tid] = local;
    __syncthreads();
    for (int off = 1; off < 1024; off <<= 1) {
        float v = (tid >= off) ? ssum[tid - off] : 0.0f;
        __syncthreads();
        ssum[tid] += v;
        __syncthreads();
    }
    float run = (tid > 0) ? ssum[tid - 1] : 0.0f;
    for (int i = lo; i < hi; i++) {
        int r = (int)run;
        d_rowstart[i] = r;
        d_cursor[i] = r;
        run += d_dis[i];
    }
    if (tid == 0) d_rowstart[N] = E;
}

__global__ void dis_kernel(int N) {
    int i = blockIdx.x * blockDim.x + threadIdx.x;
    if (i < N) d_dis[i] = rsqrtf(d_dis[i] + 1.0f);
}

__global__ void place_kernel(const void* ei, int E) {
    int e = blockIdx.x * blockDim.x + threadIdx.x;
    if (e < E) {
        int src, dst;
        edge_pair(ei, E, e, src, dst);
        int pos = atomicAdd(&d_cursor[dst], 1);
        d_csrc[pos] = src;
        d_cscale[pos] = d_dis[src];
    }
}

// -------- W prep: fragment-ordered tf32 images --------
// layout per layer (float2 entries): [c(4)][half(2)][ks(4)][nt(8)][lane(32)]
// entry value: b0 = W[k][n], b1 = W[k+4][n], k = c*32+ks*8+(lane&3),
// n = half*64 + nt*8 + (lane>>2)
__global__ void wprep_kernel(const float* __restrict__ conv_w) {
    int e = blockIdx.x * blockDim.x + threadIdx.x;  // float2 entry id
    if (e >= 3 * 8192) return;
    int lane = e & 31;
    int nt   = (e >> 5) & 7;
    int ks   = (e >> 8) & 3;
    int half = (e >> 10) & 1;
    int c    = (e >> 11) & 3;
    int l    = e >> 13;
    int kq = lane & 3, grp = lane >> 2;
    int k = c * 32 + ks * 8 + kq;
    int n = half * 64 + nt * 8 + grp;
    const float* W = conv_w + (size_t)l * H * H;
    d_wt[(size_t)e * 2 + 0] = f2tf(W[(size_t)k * H + n]);
    d_wt[(size_t)e * 2 + 1] = f2tf(W[(size_t)(k + 4) * H + n]);
}

// -------- embedding: h = x @ emb_w + emb_b  (x: [N,16], W: [16,128]) --------
__global__ void embed_kernel(const float* __restrict__ x,
                             const float* __restrict__ W,
                             const float* __restrict__ b, int N) {
    __shared__ float ws[16][H];
    __shared__ float xs[32][16];
    int tid = threadIdx.x;  // 128
    for (int i = tid; i < 16 * H; i += 128) ws[i / H][i % H] = W[i];
    float bias = b[tid];
    int n0 = blockIdx.x * 32;
    int nodes = min(32, N - n0);
    for (int i = tid; i < nodes * 16; i += 128) xs[i / 16][i % 16] = x[(size_t)n0 * 16 + i];
    __syncthreads();
    for (int n = 0; n < nodes; n++) {
        float s = bias;
#pragma unroll
        for (int k = 0; k < 16; k++) s += xs[n][k] * ws[k][tid];
        d_h[(size_t)(n0 + n) * H + tid] = s;
    }
}

// ==================== mma.sync tf32 GEMM: d_h2 = d_h @ W ====================
// 128x128 block tile, 256 threads (8 warps as 4x2), warp tile 32x64.
__global__ __launch_bounds__(256) void gemm_mma_kernel(int layer) {
    __shared__ uint32_t sA[128][36];                 // stride 36 -> conflict-free frags
    __shared__ __align__(16) uint32_t sB[4096];      // fragment-ordered chunk of W
    int tid = threadIdx.x;
    int warp = tid >> 5, lane = tid & 31;
    int wm = warp >> 1, wn = warp & 1;
    int grp = lane >> 2, kq = lane & 3;
    int row0 = blockIdx.x * 128;
    const uint32_t* wt = d_wt + (size_t)layer * (H * H);

    float acc[2][8][4];
#pragma unroll
    for (int t = 0; t < 2; t++)
#pragma unroll
        for (int nt = 0; nt < 8; nt++)
#pragma unroll
            for (int j = 0; j < 4; j++) acc[t][nt][j] = 0.0f;

    for (int c = 0; c < 4; c++) {
        // stage A chunk (tf32-converted)
#pragma unroll
        for (int v = 0; v < 4; v++) {
            int idx = v * 256 + tid;
            int r = idx >> 3, q = idx & 7;
            float4 val = *(const float4*)&d_h[(size_t)(row0 + r) * H + c * 32 + q * 4];
            uint4 u = make_uint4(f2tf(val.x), f2tf(val.y), f2tf(val.z), f2tf(val.w));
            *(uint4*)&sA[r][q * 4] = u;
        }
        // stage B chunk (already fragment-ordered tf32)
#pragma unroll
        for (int v = 0; v < 4; v++) {
            int idx = v * 256 + tid;
            *(uint4*)&sB[idx * 4] = *(const uint4*)&wt[(size_t)c * 4096 + idx * 4];
        }
        __syncthreads();
#pragma unroll
        for (int ks = 0; ks < 4; ks++) {
            uint32_t a[2][4];
#pragma unroll
            for (int t = 0; t < 2; t++) {
                int ar = wm * 32 + t * 16 + grp;
                a[t][0] = sA[ar][ks * 8 + kq];
                a[t][1] = sA[ar + 8][ks * 8 + kq];
                a[t][2] = sA[ar][ks * 8 + kq + 4];
                a[t][3] = sA[ar + 8][ks * 8 + kq + 4];
            }
#pragma unroll
            for (int nt = 0; nt < 8; nt++) {
                uint2 b = *(const uint2*)&sB[(((wn * 4 + ks) * 8 + nt) * 32 + lane) * 2];
                MMA_TF32(acc[0][nt], a[0], b.x, b.y);
                MMA_TF32(acc[1][nt], a[1], b.x, b.y);
            }
        }
        __syncthreads();
    }
#pragma unroll
    for (int t = 0; t < 2; t++) {
        int r = row0 + wm * 32 + t * 16 + grp;
#pragma unroll
        for (int nt = 0; nt < 8; nt++) {
            int col = wn * 64 + nt * 8 + kq * 2;
            *(float2*)&d_h2[(size_t)r * H + col] = make_float2(acc[t][nt][0], acc[t][nt][1]);
            *(float2*)&d_h2[(size_t)(r + 8) * H + col] = make_float2(acc[t][nt][2], acc[t][nt][3]);
        }
    }
}

// -------- fused gather + combine: one warp per dst node --------
__global__ void gather_kernel(const float* __restrict__ b, int N) {
    int w = (blockIdx.x * blockDim.x + threadIdx.x) >> 5;
    if (w >= N) return;
    int lane = threadIdx.x & 31;
    int beg = d_rowstart[w], end = d_rowstart[w + 1];
    float ax = 0.f, ay = 0.f, az = 0.f, aw = 0.f;
    int i = beg;
    for (; i + 2 <= end; i += 2) {
        int s0 = d_csrc[i], s1 = d_csrc[i + 1];
        float c0 = d_cscale[i], c1 = d_cscale[i + 1];
        float4 v0 = *(const float4*)&d_h2[(size_t)s0 * H + lane * 4];
        float4 v1 = *(const float4*)&d_h2[(size_t)s1 * H + lane * 4];
        ax += v0.x * c0; ay += v0.y * c0; az += v0.z * c0; aw += v0.w * c0;
        ax += v1.x * c1; ay += v1.y * c1; az += v1.z * c1; aw += v1.w * c1;
    }
    if (i < end) {
        int s0 = d_csrc[i];
        float c0 = d_cscale[i];
        float4 v0 = *(const float4*)&d_h2[(size_t)s0 * H + lane * 4];
        ax += v0.x * c0; ay += v0.y * c0; az += v0.z * c0; aw += v0.w * c0;
    }
    float dd = d_dis[w];
    float dd2 = dd * dd;
    float4 hv = *(const float4*)&d_h2[(size_t)w * H + lane * 4];
    float4 bb = *(const float4*)&b[lane * 4];
    float4 o;
    o.x = fmaxf(ax * dd + hv.x * dd2 + bb.x, 0.0f);
    o.y = fmaxf(ay * dd + hv.y * dd2 + bb.y, 0.0f);
    o.z = fmaxf(az * dd + hv.z * dd2 + bb.z, 0.0f);
    o.w = fmaxf(aw * dd + hv.w * dd2 + bb.w, 0.0f);
    *(float4*)&d_h[(size_t)w * H + lane * 4] = o;
}

// -------- global mean pool: column sums into d_g --------
__global__ void colsum_kernel(int N) {
    int col = threadIdx.x;  // 128
    float s = 0.0f;
    for (int n = blockIdx.x; n < N; n += gridDim.x)
        s += d_h[(size_t)n * H + col];
    atomicAdd(&d_g[col], s);
}

// -------- MLP head --------
__global__ void head_kernel(const float* __restrict__ fc1w, const float* __restrict__ fc1b,
                            const float* __restrict__ fc2w, const float* __restrict__ fc2b,
                            float* __restrict__ out, int N) {
    __shared__ float sg[H], sg1[H];
    int tid = threadIdx.x;  // 128
    sg[tid] = d_g[tid] / (float)N;
    __syncthreads();
    float s = fc1b[tid];
#pragma unroll 16
    for (int k = 0; k < H; k++) s += sg[k] * fc1w[(size_t)k * H + tid];
    sg1[tid] = fmaxf(s, 0.0f);
    __syncthreads();
    if (tid < 64) {
        float o = fc2b[tid];
#pragma unroll 16
        for (int k = 0; k < H; k++) o += sg1[k] * fc2w[(size_t)k * 64 + tid];
        out[tid] = o;
    }
}

extern "C" void kernel_launch(void* const* d_in, const int* in_sizes, int n_in,
                              void* d_out, int out_size) {
    const float* x      = (const float*)d_in[0];
    const void*  ei     = d_in[1];
    const float* emb_w  = (const float*)d_in[2];
    const float* emb_b  = (const float*)d_in[3];
    const float* conv_w = (const float*)d_in[4];
    const float* conv_b = (const float*)d_in[5];
    const float* fc1_w  = (const float*)d_in[6];
    const float* fc1_b  = (const float*)d_in[7];
    const float* fc2_w  = (const float*)d_in[8];
    const float* fc2_b  = (const float*)d_in[9];
    float* out = (float*)d_out;

    int N = in_sizes[0] / 16;   // 100000
    int E = in_sizes[1] / 2;    // 1600000

    void *dis_p, *g_p;
    cudaGetSymbolAddress(&dis_p, d_dis);
    cudaGetSymbolAddress(&g_p, d_g);
    cudaMemsetAsync(dis_p, 0, (size_t)N * sizeof(float));
    cudaMemsetAsync(g_p, 0, H * sizeof(float));

    detect_kernel<<<1, 32>>>((const int*)ei, E);
    degree_kernel<<<(E + 255) / 256, 256>>>(ei, E);
    scan_kernel<<<1, 1024>>>(N, E);
    dis_kernel<<<(N + 255) / 256, 256>>>(N);
    place_kernel<<<(E + 255) / 256, 256>>>(ei, E);
    wprep_kernel<<<96, 256>>>(conv_w);
    embed_kernel<<<(N + 31) / 32, 128>>>(x, emb_w, emb_b, N);

    int gblocks = (int)(((long long)N * 32 + 255) / 256);
    int gemmblocks = (N + 127) / 128;   // 782 -> exactly NPAD rows

    for (int l = 0; l < 3; l++) {
        gemm_mma_kernel<<<gemmblocks, 256>>>(l);
        gather_kernel<<<gblocks, 256>>>(conv_b + (size_t)l * H, N);
    }

    colsum_kernel<<<512, 128>>>(N);
    head_kernel<<<1, 128>>>(fc1_w, fc1_b, fc2_w, fc2_b, out, N);
}

// round 5
// speedup vs baseline: 2.3571x; 1.0576x over previous
#include <cuda_runtime.h>
#include <cuda_bf16.h>
#include <cstdint>

#define NMAX 100000
#define NPAD 100096
#define EMAX 1600000
#define H 128

// -------- scratch (device globals; no allocation allowed) --------
__device__ float         d_h  [(size_t)NPAD * H];  // node features (padded; pad rows stay 0)
__device__ __nv_bfloat16 d_h2b[(size_t)NPAD * H];  // h @ W  (bf16)
__device__ float         d_dis[NMAX];              // degree count -> rsqrt(deg+1)
__device__ int           d_rowstart[NMAX + 1];     // CSR row offsets (by dst)
__device__ int           d_cursor[NMAX];           // placement cursors
__device__ int           d_csrc[EMAX];             // CSR src indices
__device__ float         d_cscale[EMAX];           // dis[src] per edge
__device__ uint32_t      d_wt[3 * H * H];          // fragment-ordered tf32 W images
__device__ float         d_g[H];                   // column sums for mean pool
__device__ int           d_is64;                   // edge_index is int64?

__device__ __forceinline__ uint32_t f2tf(float f) {
    uint32_t u;
    asm("cvt.rna.tf32.f32 %0, %1;" : "=r"(u) : "f"(f));
    return u;
}

#define MMA_TF32(c, a, b0, b1)                                                 \
    asm volatile("mma.sync.aligned.m16n8k8.row.col.f32.tf32.tf32.f32 "         \
        "{%0,%1,%2,%3}, {%4,%5,%6,%7}, {%8,%9}, {%0,%1,%2,%3};"                \
        : "+f"((c)[0]), "+f"((c)[1]), "+f"((c)[2]), "+f"((c)[3])               \
        : "r"((a)[0]), "r"((a)[1]), "r"((a)[2]), "r"((a)[3]),                  \
          "r"(b0), "r"(b1))

// ==================== preprocessing ====================
__global__ void detect_kernel(const int* ei, int E) {
    if (threadIdx.x == 0 && blockIdx.x == 0) {
        int n = E < 64 ? E : 64;
        int all0 = 1;
        for (int i = 0; i < n; i++)
            if (ei[2 * i + 1] != 0) { all0 = 0; break; }
        d_is64 = all0;
    }
}

__device__ __forceinline__ void edge_pair(const void* ei, int E, int e, int& src, int& dst) {
    if (d_is64) {
        const long long* p = (const long long*)ei;
        src = (int)p[e];
        dst = (int)p[(long long)E + e];
    } else {
        const int* p = (const int*)ei;
        src = p[e];
        dst = p[E + e];
    }
}

__global__ void degree_kernel(const void* ei, int E) {
    int e = blockIdx.x * blockDim.x + threadIdx.x;
    if (e < E) {
        int src, dst;
        edge_pair(ei, E, e, src, dst);
        atomicAdd(&d_dis[dst], 1.0f);
    }
}

// scan of degrees -> rowstart & cursor; also transforms d_dis -> rsqrt(deg+1)
__global__ void scan_kernel(int N, int E) {
    __shared__ float ssum[1024];
    int tid = threadIdx.x;
    int C = (N + 1023) / 1024;
    int lo = tid * C, hi = min(lo + C, N);
    float local = 0.0f;
    for (int i = lo; i < hi; i++) local += d_dis[i];
    ssum[tid] = local;
    __syncthreads();
    for (int off = 1; off < 1024; off <<= 1) {
        float v = (tid >= off) ? ssum[tid - off] : 0.0f;
        __syncthreads();
        ssum[tid] += v;
        __syncthreads();
    }
    float run = (tid > 0) ? ssum[tid - 1] : 0.0f;
    for (int i = lo; i < hi; i++) {
        float deg = d_dis[i];
        int r = (int)run;
        d_rowstart[i] = r;
        d_cursor[i] = r;
        run += deg;
        d_dis[i] = rsqrtf(deg + 1.0f);
    }
    if (tid == 0) d_rowstart[N] = E;
}

__global__ void place_kernel(const void* ei, int E) {
    int e = blockIdx.x * blockDim.x + threadIdx.x;
    if (e < E) {
        int src, dst;
        edge_pair(ei, E, e, src, dst);
        int pos = atomicAdd(&d_cursor[dst], 1);
        d_csrc[pos] = src;
        d_cscale[pos] = d_dis[src];
    }
}

// -------- W prep: fragment-ordered tf32 images --------
__global__ void wprep_kernel(const float* __restrict__ conv_w) {
    int e = blockIdx.x * blockDim.x + threadIdx.x;  // float2 entry id
    if (e >= 3 * 8192) return;
    int lane = e & 31;
    int nt   = (e >> 5) & 7;
    int ks   = (e >> 8) & 3;
    int half = (e >> 10) & 1;
    int c    = (e >> 11) & 3;
    int l    = e >> 13;
    int kq = lane & 3, grp = lane >> 2;
    int k = c * 32 + ks * 8 + kq;
    int n = half * 64 + nt * 8 + grp;
    const float* W = conv_w + (size_t)l * H * H;
    d_wt[(size_t)e * 2 + 0] = f2tf(W[(size_t)k * H + n]);
    d_wt[(size_t)e * 2 + 1] = f2tf(W[(size_t)(k + 4) * H + n]);
}

// -------- embedding: h = x @ emb_w + emb_b  (x: [N,16], W: [16,128]) --------
__global__ void embed_kernel(const float* __restrict__ x,
                             const float* __restrict__ W,
                             const float* __restrict__ b, int N) {
    __shared__ float ws[16][H];
    __shared__ float xs[32][16];
    int tid = threadIdx.x;  // 128
    for (int i = tid; i < 16 * H; i += 128) ws[i / H][i % H] = W[i];
    float bias = b[tid];
    int n0 = blockIdx.x * 32;
    int nodes = min(32, N - n0);
    for (int i = tid; i < nodes * 16; i += 128) xs[i / 16][i % 16] = x[(size_t)n0 * 16 + i];
    __syncthreads();
    for (int n = 0; n < nodes; n++) {
        float s = bias;
#pragma unroll
        for (int k = 0; k < 16; k++) s += xs[n][k] * ws[k][tid];
        d_h[(size_t)(n0 + n) * H + tid] = s;
    }
}

// ==================== mma.sync tf32 GEMM: d_h2b = bf16(d_h @ W) ====================
__global__ __launch_bounds__(256) void gemm_mma_kernel(int layer) {
    __shared__ uint32_t sA[128][36];
    __shared__ __align__(16) uint32_t sB[4096];
    int tid = threadIdx.x;
    int warp = tid >> 5, lane = tid & 31;
    int wm = warp >> 1, wn = warp & 1;
    int grp = lane >> 2, kq = lane & 3;
    int row0 = blockIdx.x * 128;
    const uint32_t* wt = d_wt + (size_t)layer * (H * H);

    float acc[2][8][4];
#pragma unroll
    for (int t = 0; t < 2; t++)
#pragma unroll
        for (int nt = 0; nt < 8; nt++)
#pragma unroll
            for (int j = 0; j < 4; j++) acc[t][nt][j] = 0.0f;

    for (int c = 0; c < 4; c++) {
#pragma unroll
        for (int v = 0; v < 4; v++) {
            int idx = v * 256 + tid;
            int r = idx >> 3, q = idx & 7;
            float4 val = *(const float4*)&d_h[(size_t)(row0 + r) * H + c * 32 + q * 4];
            uint4 u = make_uint4(f2tf(val.x), f2tf(val.y), f2tf(val.z), f2tf(val.w));
            *(uint4*)&sA[r][q * 4] = u;
        }
#pragma unroll
        for (int v = 0; v < 4; v++) {
            int idx = v * 256 + tid;
            *(uint4*)&sB[idx * 4] = *(const uint4*)&wt[(size_t)c * 4096 + idx * 4];
        }
        __syncthreads();
#pragma unroll
        for (int ks = 0; ks < 4; ks++) {
            uint32_t a[2][4];
#pragma unroll
            for (int t = 0; t < 2; t++) {
                int ar = wm * 32 + t * 16 + grp;
                a[t][0] = sA[ar][ks * 8 + kq];
                a[t][1] = sA[ar + 8][ks * 8 + kq];
                a[t][2] = sA[ar][ks * 8 + kq + 4];
                a[t][3] = sA[ar + 8][ks * 8 + kq + 4];
            }
#pragma unroll
            for (int nt = 0; nt < 8; nt++) {
                uint2 b = *(const uint2*)&sB[(((wn * 4 + ks) * 8 + nt) * 32 + lane) * 2];
                MMA_TF32(acc[0][nt], a[0], b.x, b.y);
                MMA_TF32(acc[1][nt], a[1], b.x, b.y);
            }
        }
        __syncthreads();
    }
#pragma unroll
    for (int t = 0; t < 2; t++) {
        int r = row0 + wm * 32 + t * 16 + grp;
#pragma unroll
        for (int nt = 0; nt < 8; nt++) {
            int col = wn * 64 + nt * 8 + kq * 2;
            *(__nv_bfloat162*)&d_h2b[(size_t)r * H + col] =
                __float22bfloat162_rn(make_float2(acc[t][nt][0], acc[t][nt][1]));
            *(__nv_bfloat162*)&d_h2b[(size_t)(r + 8) * H + col] =
                __float22bfloat162_rn(make_float2(acc[t][nt][2], acc[t][nt][3]));
        }
    }
}

// -------- fused gather + combine: one warp per dst node (bf16 sources) --------
__global__ void gather_kernel(const float* __restrict__ b, int N) {
    int w = (blockIdx.x * blockDim.x + threadIdx.x) >> 5;
    if (w >= N) return;
    int lane = threadIdx.x & 31;
    int beg = d_rowstart[w], end = d_rowstart[w + 1];
    float ax = 0.f, ay = 0.f, az = 0.f, aw = 0.f;
    int i = beg;
    for (; i + 2 <= end; i += 2) {
        int s0 = d_csrc[i], s1 = d_csrc[i + 1];
        float c0 = d_cscale[i], c1 = d_cscale[i + 1];
        uint2 u0 = *(const uint2*)&d_h2b[(size_t)s0 * H + lane * 4];
        uint2 u1 = *(const uint2*)&d_h2b[(size_t)s1 * H + lane * 4];
        float2 p0 = __bfloat1622float2(*(__nv_bfloat162*)&u0.x);
        float2 p1 = __bfloat1622float2(*(__nv_bfloat162*)&u0.y);
        float2 p2 = __bfloat1622float2(*(__nv_bfloat162*)&u1.x);
        float2 p3 = __bfloat1622float2(*(__nv_bfloat162*)&u1.y);
        ax += p0.x * c0; ay += p0.y * c0; az += p1.x * c0; aw += p1.y * c0;
        ax += p2.x * c1; ay += p2.y * c1; az += p3.x * c1; aw += p3.y * c1;
    }
    if (i < end) {
        int s0 = d_csrc[i];
        float c0 = d_cscale[i];
        uint2 u0 = *(const uint2*)&d_h2b[(size_t)s0 * H + lane * 4];
        float2 p0 = __bfloat1622float2(*(__nv_bfloat162*)&u0.x);
        float2 p1 = __bfloat1622float2(*(__nv_bfloat162*)&u0.y);
        ax += p0.x * c0; ay += p0.y * c0; az += p1.x * c0; aw += p1.y * c0;
    }
    float dd = d_dis[w];
    float dd2 = dd * dd;
    uint2 us = *(const uint2*)&d_h2b[(size_t)w * H + lane * 4];
    float2 h0 = __bfloat1622float2(*(__nv_bfloat162*)&us.x);
    float2 h1 = __bfloat1622float2(*(__nv_bfloat162*)&us.y);
    float4 bb = *(const float4*)&b[lane * 4];
    float4 o;
    o.x = fmaxf(ax * dd + h0.x * dd2 + bb.x, 0.0f);
    o.y = fmaxf(ay * dd + h0.y * dd2 + bb.y, 0.0f);
    o.z = fmaxf(az * dd + h1.x * dd2 + bb.z, 0.0f);
    o.w = fmaxf(aw * dd + h1.y * dd2 + bb.w, 0.0f);
    *(float4*)&d_h[(size_t)w * H + lane * 4] = o;
}

// -------- global mean pool: column sums into d_g --------
__global__ void colsum_kernel(int N) {
    int col = threadIdx.x;  // 128
    float s = 0.0f;
    for (int n = blockIdx.x; n < N; n += gridDim.x)
        s += d_h[(size_t)n * H + col];
    atomicAdd(&d_g[col], s);
}

// -------- MLP head --------
__global__ void head_kernel(const float* __restrict__ fc1w, const float* __restrict__ fc1b,
                            const float* __restrict__ fc2w, const float* __restrict__ fc2b,
                            float* __restrict__ out, int N) {
    __shared__ float sg[H], sg1[H];
    int tid = threadIdx.x;  // 128
    sg[tid] = d_g[tid] / (float)N;
    __syncthreads();
    float s = fc1b[tid];
#pragma unroll 16
    for (int k = 0; k < H; k++) s += sg[k] * fc1w[(size_t)k * H + tid];
    sg1[tid] = fmaxf(s, 0.0f);
    __syncthreads();
    if (tid < 64) {
        float o = fc2b[tid];
#pragma unroll 16
        for (int k = 0; k < H; k++) o += sg1[k] * fc2w[(size_t)k * 64 + tid];
        out[tid] = o;
    }
}

extern "C" void kernel_launch(void* const* d_in, const int* in_sizes, int n_in,
                              void* d_out, int out_size) {
    const float* x      = (const float*)d_in[0];
    const void*  ei     = d_in[1];
    const float* emb_w  = (const float*)d_in[2];
    const float* emb_b  = (const float*)d_in[3];
    const float* conv_w = (const float*)d_in[4];
    const float* conv_b = (const float*)d_in[5];
    const float* fc1_w  = (const float*)d_in[6];
    const float* fc1_b  = (const float*)d_in[7];
    const float* fc2_w  = (const float*)d_in[8];
    const float* fc2_b  = (const float*)d_in[9];
    float* out = (float*)d_out;

    int N = in_sizes[0] / 16;   // 100000
    int E = in_sizes[1] / 2;    // 1600000

    void *dis_p, *g_p;
    cudaGetSymbolAddress(&dis_p, d_dis);
    cudaGetSymbolAddress(&g_p, d_g);
    cudaMemsetAsync(dis_p, 0, (size_t)N * sizeof(float));
    cudaMemsetAsync(g_p, 0, H * sizeof(float));

    detect_kernel<<<1, 32>>>((const int*)ei, E);
    degree_kernel<<<(E + 255) / 256, 256>>>(ei, E);
    scan_kernel<<<1, 1024>>>(N, E);
    place_kernel<<<(E + 255) / 256, 256>>>(ei, E);
    wprep_kernel<<<96, 256>>>(conv_w);
    embed_kernel<<<(N + 31) / 32, 128>>>(x, emb_w, emb_b, N);

    int gblocks = (int)(((long long)N * 32 + 255) / 256);
    int gemmblocks = (N + 127) / 128;   // 782 -> exactly NPAD rows

    for (int l = 0; l < 3; l++) {
        gemm_mma_kernel<<<gemmblocks, 256>>>(l);
        gather_kernel<<<gblocks, 256>>>(conv_b + (size_t)l * H, N);
    }

    colsum_kernel<<<512, 128>>>(N);
    head_kernel<<<1, 128>>>(fc1_w, fc1_b, fc2_w, fc2_b, out, N);
}

// round 6
// speedup vs baseline: 3.9476x; 1.6747x over previous
#include <cuda_runtime.h>
#include <cuda_bf16.h>
#include <cstdint>

#define NMAX 100000
#define NPAD 100096
#define EMAX 1600000
#define H 128

// -------- scratch (device globals; no allocation allowed) --------
__device__ __nv_bfloat16 d_hb [(size_t)NPAD * H];  // node features (bf16; pad rows stay 0)
__device__ __nv_bfloat16 d_h2b[(size_t)NPAD * H];  // h @ W (bf16)
__device__ float         d_dis[NMAX];              // degree count -> rsqrt(deg+1)
__device__ int           d_rowstart[NMAX + 1];     // CSR row offsets (by dst)
__device__ int           d_cursor[NMAX];           // placement cursors
__device__ int2          d_edge[EMAX];             // packed (src, dis[src] bits)
__device__ float         d_bsum[64];               // scan block sums
__device__ float         d_boff[64];               // scan block offsets
__device__ uint32_t      d_wt[3 * H * H];          // fragment-ordered tf32 W images
__device__ float         d_g[H];                   // column sums for mean pool
__device__ int           d_is64;                   // edge_index is int64?

__device__ __forceinline__ uint32_t f2tf(float f) {
    uint32_t u;
    asm("cvt.rna.tf32.f32 %0, %1;" : "=r"(u) : "f"(f));
    return u;
}

#define MMA_TF32(c, a, b0, b1)                                                 \
    asm volatile("mma.sync.aligned.m16n8k8.row.col.f32.tf32.tf32.f32 "         \
        "{%0,%1,%2,%3}, {%4,%5,%6,%7}, {%8,%9}, {%0,%1,%2,%3};"                \
        : "+f"((c)[0]), "+f"((c)[1]), "+f"((c)[2]), "+f"((c)[3])               \
        : "r"((a)[0]), "r"((a)[1]), "r"((a)[2]), "r"((a)[3]),                  \
          "r"(b0), "r"(b1))

// ==================== preprocessing ====================
__global__ void detect_kernel(const int* ei, int E) {
    if (threadIdx.x == 0 && blockIdx.x == 0) {
        int n = E < 64 ? E : 64;
        int all0 = 1;
        for (int i = 0; i < n; i++)
            if (ei[2 * i + 1] != 0) { all0 = 0; break; }
        d_is64 = all0;
    }
}

__device__ __forceinline__ void edge_pair(const void* ei, int E, int e, int& src, int& dst) {
    if (d_is64) {
        const long long* p = (const long long*)ei;
        src = (int)p[e];
        dst = (int)p[(long long)E + e];
    } else {
        const int* p = (const int*)ei;
        src = p[e];
        dst = p[E + e];
    }
}

__global__ void degree_kernel(const void* ei, int E) {
    int e = blockIdx.x * blockDim.x + threadIdx.x;
    if (e < E) {
        int dst;
        if (d_is64) dst = (int)((const long long*)ei)[(long long)E + e];
        else        dst = ((const int*)ei)[E + e];
        atomicAdd(&d_dis[dst], 1.0f);
    }
}

// -------- parallel 3-phase scan --------
// phase 1: per-block (2048 elems) exclusive prefix into d_rowstart, block sum out
__global__ void scan_part(int N) {
    __shared__ float ss[1024];
    int b = blockIdx.x, tid = threadIdx.x;
    int i0 = b * 2048 + 2 * tid, i1 = i0 + 1;
    float a = (i0 < N) ? d_dis[i0] : 0.0f;
    float c = (i1 < N) ? d_dis[i1] : 0.0f;
    ss[tid] = a + c;
    __syncthreads();
    for (int off = 1; off < 1024; off <<= 1) {
        float v = (tid >= off) ? ss[tid - off] : 0.0f;
        __syncthreads();
        ss[tid] += v;
        __syncthreads();
    }
    float excl = (tid > 0) ? ss[tid - 1] : 0.0f;
    if (i0 < N) d_rowstart[i0] = (int)excl;
    if (i1 < N) d_rowstart[i1] = (int)(excl + a);
    if (tid == 1023) d_bsum[b] = ss[1023];
}

// phase 2: scan of block sums (<=64 blocks)
__global__ void scan_mid(int nb) {
    __shared__ float ss[64];
    int tid = threadIdx.x;  // 64
    float v = (tid < nb) ? d_bsum[tid] : 0.0f;
    ss[tid] = v;
    __syncthreads();
    for (int off = 1; off < 64; off <<= 1) {
        float u = (tid >= off) ? ss[tid - off] : 0.0f;
        __syncthreads();
        ss[tid] += u;
        __syncthreads();
    }
    d_boff[tid] = (tid > 0) ? ss[tid - 1] : 0.0f;
}

// phase 3: apply block offsets; init cursor; dis transform
__global__ void scan_apply(int N, int E) {
    int i = blockIdx.x * blockDim.x + threadIdx.x;
    if (i < N) {
        int r = d_rowstart[i] + (int)d_boff[i >> 11];
        d_rowstart[i] = r;
        d_cursor[i] = r;
        d_dis[i] = rsqrtf(d_dis[i] + 1.0f);
    }
    if (i == 0) d_rowstart[N] = E;
}

__global__ void place_kernel(const void* ei, int E) {
    int e = blockIdx.x * blockDim.x + threadIdx.x;
    if (e < E) {
        int src, dst;
        edge_pair(ei, E, e, src, dst);
        int pos = atomicAdd(&d_cursor[dst], 1);
        d_edge[pos] = make_int2(src, __float_as_int(d_dis[src]));
    }
}

// -------- W prep: fragment-ordered tf32 images --------
__global__ void wprep_kernel(const float* __restrict__ conv_w) {
    int e = blockIdx.x * blockDim.x + threadIdx.x;  // float2 entry id
    if (e >= 3 * 8192) return;
    int lane = e & 31;
    int nt   = (e >> 5) & 7;
    int ks   = (e >> 8) & 3;
    int half = (e >> 10) & 1;
    int c    = (e >> 11) & 3;
    int l    = e >> 13;
    int kq = lane & 3, grp = lane >> 2;
    int k = c * 32 + ks * 8 + kq;
    int n = half * 64 + nt * 8 + grp;
    const float* W = conv_w + (size_t)l * H * H;
    d_wt[(size_t)e * 2 + 0] = f2tf(W[(size_t)k * H + n]);
    d_wt[(size_t)e * 2 + 1] = f2tf(W[(size_t)(k + 4) * H + n]);
}

// -------- embedding: h = x @ emb_w + emb_b --------
__global__ void embed_kernel(const float* __restrict__ x,
                             const float* __restrict__ W,
                             const float* __restrict__ b, int N) {
    __shared__ float ws[16][H];
    __shared__ float xs[32][16];
    int tid = threadIdx.x;  // 128
    for (int i = tid; i < 16 * H; i += 128) ws[i / H][i % H] = W[i];
    float bias = b[tid];
    int n0 = blockIdx.x * 32;
    int nodes = min(32, N - n0);
    for (int i = tid; i < nodes * 16; i += 128) xs[i / 16][i % 16] = x[(size_t)n0 * 16 + i];
    __syncthreads();
    for (int n = 0; n < nodes; n++) {
        float s = bias;
#pragma unroll
        for (int k = 0; k < 16; k++) s += xs[n][k] * ws[k][tid];
        d_hb[(size_t)(n0 + n) * H + tid] = __float2bfloat16(s);
    }
}

// ==================== mma.sync tf32 GEMM: d_h2b = bf16(d_hb @ W) ====================
__global__ __launch_bounds__(256) void gemm_mma_kernel(int layer) {
    __shared__ uint32_t sA[128][36];
    __shared__ __align__(16) uint32_t sB[4096];
    int tid = threadIdx.x;
    int warp = tid >> 5, lane = tid & 31;
    int wm = warp >> 1, wn = warp & 1;
    int grp = lane >> 2, kq = lane & 3;
    int row0 = blockIdx.x * 128;
    const uint32_t* wt = d_wt + (size_t)layer * (H * H);

    float acc[2][8][4];
#pragma unroll
    for (int t = 0; t < 2; t++)
#pragma unroll
        for (int nt = 0; nt < 8; nt++)
#pragma unroll
            for (int j = 0; j < 4; j++) acc[t][nt][j] = 0.0f;

    for (int c = 0; c < 4; c++) {
        // stage A chunk: bf16 -> tf32
#pragma unroll
        for (int v = 0; v < 2; v++) {
            int idx = v * 256 + tid;        // 0..511, each covers 8 bf16
            int r = idx >> 2, q = idx & 3;
            uint4 u = *(const uint4*)&d_hb[(size_t)(row0 + r) * H + c * 32 + q * 8];
            float2 p0 = __bfloat1622float2(*(__nv_bfloat162*)&u.x);
            float2 p1 = __bfloat1622float2(*(__nv_bfloat162*)&u.y);
            float2 p2 = __bfloat1622float2(*(__nv_bfloat162*)&u.z);
            float2 p3 = __bfloat1622float2(*(__nv_bfloat162*)&u.w);
            uint4 o0 = make_uint4(f2tf(p0.x), f2tf(p0.y), f2tf(p1.x), f2tf(p1.y));
            uint4 o1 = make_uint4(f2tf(p2.x), f2tf(p2.y), f2tf(p3.x), f2tf(p3.y));
            *(uint4*)&sA[r][q * 8 + 0] = o0;
            *(uint4*)&sA[r][q * 8 + 4] = o1;
        }
#pragma unroll
        for (int v = 0; v < 4; v++) {
            int idx = v * 256 + tid;
            *(uint4*)&sB[idx * 4] = *(const uint4*)&wt[(size_t)c * 4096 + idx * 4];
        }
        __syncthreads();
#pragma unroll
        for (int ks = 0; ks < 4; ks++) {
            uint32_t a[2][4];
#pragma unroll
            for (int t = 0; t < 2; t++) {
                int ar = wm * 32 + t * 16 + grp;
                a[t][0] = sA[ar][ks * 8 + kq];
                a[t][1] = sA[ar + 8][ks * 8 + kq];
                a[t][2] = sA[ar][ks * 8 + kq + 4];
                a[t][3] = sA[ar + 8][ks * 8 + kq + 4];
            }
#pragma unroll
            for (int nt = 0; nt < 8; nt++) {
                uint2 b = *(const uint2*)&sB[(((wn * 4 + ks) * 8 + nt) * 32 + lane) * 2];
                MMA_TF32(acc[0][nt], a[0], b.x, b.y);
                MMA_TF32(acc[1][nt], a[1], b.x, b.y);
            }
        }
        __syncthreads();
    }
#pragma unroll
    for (int t = 0; t < 2; t++) {
        int r = row0 + wm * 32 + t * 16 + grp;
#pragma unroll
        for (int nt = 0; nt < 8; nt++) {
            int col = wn * 64 + nt * 8 + kq * 2;
            *(__nv_bfloat162*)&d_h2b[(size_t)r * H + col] =
                __float22bfloat162_rn(make_float2(acc[t][nt][0], acc[t][nt][1]));
            *(__nv_bfloat162*)&d_h2b[(size_t)(r + 8) * H + col] =
                __float22bfloat162_rn(make_float2(acc[t][nt][2], acc[t][nt][3]));
        }
    }
}

// -------- fused gather + combine: one warp per dst node --------
__device__ __forceinline__ void acc_row(int src, float cf, int lane,
                                        float& ax, float& ay, float& az, float& aw) {
    uint2 u = *(const uint2*)&d_h2b[(size_t)src * H + lane * 4];
    float2 p0 = __bfloat1622float2(*(__nv_bfloat162*)&u.x);
    float2 p1 = __bfloat1622float2(*(__nv_bfloat162*)&u.y);
    ax += p0.x * cf; ay += p0.y * cf; az += p1.x * cf; aw += p1.y * cf;
}

__global__ void gather_kernel(const float* __restrict__ b, int N) {
    int w = (blockIdx.x * blockDim.x + threadIdx.x) >> 5;
    if (w >= N) return;
    int lane = threadIdx.x & 31;
    int beg = d_rowstart[w], end = d_rowstart[w + 1];
    float ax = 0.f, ay = 0.f, az = 0.f, aw = 0.f;
    int i = beg;
    for (; i + 4 <= end; i += 4) {
        int2 e0 = d_edge[i], e1 = d_edge[i + 1], e2 = d_edge[i + 2], e3 = d_edge[i + 3];
        acc_row(e0.x, __int_as_float(e0.y), lane, ax, ay, az, aw);
        acc_row(e1.x, __int_as_float(e1.y), lane, ax, ay, az, aw);
        acc_row(e2.x, __int_as_float(e2.y), lane, ax, ay, az, aw);
        acc_row(e3.x, __int_as_float(e3.y), lane, ax, ay, az, aw);
    }
    for (; i < end; i++) {
        int2 e0 = d_edge[i];
        acc_row(e0.x, __int_as_float(e0.y), lane, ax, ay, az, aw);
    }
    float dd = d_dis[w];
    float dd2 = dd * dd;
    uint2 us = *(const uint2*)&d_h2b[(size_t)w * H + lane * 4];
    float2 h0 = __bfloat1622float2(*(__nv_bfloat162*)&us.x);
    float2 h1 = __bfloat1622float2(*(__nv_bfloat162*)&us.y);
    float4 bb = *(const float4*)&b[lane * 4];
    __nv_bfloat162 o0 = __float22bfloat162_rn(make_float2(
        fmaxf(ax * dd + h0.x * dd2 + bb.x, 0.0f),
        fmaxf(ay * dd + h0.y * dd2 + bb.y, 0.0f)));
    __nv_bfloat162 o1 = __float22bfloat162_rn(make_float2(
        fmaxf(az * dd + h1.x * dd2 + bb.z, 0.0f),
        fmaxf(aw * dd + h1.y * dd2 + bb.w, 0.0f)));
    uint2 st;
    st.x = *(uint32_t*)&o0;
    st.y = *(uint32_t*)&o1;
    *(uint2*)&d_hb[(size_t)w * H + lane * 4] = st;
}

// -------- global mean pool: column sums into d_g --------
__global__ void colsum_kernel(int N) {
    int col = threadIdx.x;  // 128
    float s = 0.0f;
    for (int n = blockIdx.x; n < N; n += gridDim.x)
        s += __bfloat162float(d_hb[(size_t)n * H + col]);
    atomicAdd(&d_g[col], s);
}

// -------- MLP head --------
__global__ void head_kernel(const float* __restrict__ fc1w, const float* __restrict__ fc1b,
                            const float* __restrict__ fc2w, const float* __restrict__ fc2b,
                            float* __restrict__ out, int N) {
    __shared__ float sg[H], sg1[H];
    int tid = threadIdx.x;  // 128
    sg[tid] = d_g[tid] / (float)N;
    __syncthreads();
    float s = fc1b[tid];
#pragma unroll 16
    for (int k = 0; k < H; k++) s += sg[k] * fc1w[(size_t)k * H + tid];
    sg1[tid] = fmaxf(s, 0.0f);
    __syncthreads();
    if (tid < 64) {
        float o = fc2b[tid];
#pragma unroll 16
        for (int k = 0; k < H; k++) o += sg1[k] * fc2w[(size_t)k * 64 + tid];
        out[tid] = o;
    }
}

extern "C" void kernel_launch(void* const* d_in, const int* in_sizes, int n_in,
                              void* d_out, int out_size) {
    const float* x      = (const float*)d_in[0];
    const void*  ei     = d_in[1];
    const float* emb_w  = (const float*)d_in[2];
    const float* emb_b  = (const float*)d_in[3];
    const float* conv_w = (const float*)d_in[4];
    const float* conv_b = (const float*)d_in[5];
    const float* fc1_w  = (const float*)d_in[6];
    const float* fc1_b  = (const float*)d_in[7];
    const float* fc2_w  = (const float*)d_in[8];
    const float* fc2_b  = (const float*)d_in[9];
    float* out = (float*)d_out;

    int N = in_sizes[0] / 16;   // 100000
    int E = in_sizes[1] / 2;    // 1600000

    void *dis_p, *g_p;
    cudaGetSymbolAddress(&dis_p, d_dis);
    cudaGetSymbolAddress(&g_p, d_g);
    cudaMemsetAsync(dis_p, 0, (size_t)N * sizeof(float));
    cudaMemsetAsync(g_p, 0, H * sizeof(float));

    int nb = (N + 2047) / 2048;   // scan blocks (<= 64)

    detect_kernel<<<1, 32>>>((const int*)ei, E);
    degree_kernel<<<(E + 255) / 256, 256>>>(ei, E);
    scan_part<<<nb, 1024>>>(N);
    scan_mid<<<1, 64>>>(nb);
    scan_apply<<<(N + 255) / 256, 256>>>(N, E);
    place_kernel<<<(E + 255) / 256, 256>>>(ei, E);
    wprep_kernel<<<96, 256>>>(conv_w);
    embed_kernel<<<(N + 31) / 32, 128>>>(x, emb_w, emb_b, N);

    int gblocks = (int)(((long long)N * 32 + 255) / 256);
    int gemmblocks = (N + 127) / 128;   // 782 -> exactly NPAD rows

    for (int l = 0; l < 3; l++) {
        gemm_mma_kernel<<<gemmblocks, 256>>>(l);
        gather_kernel<<<gblocks, 256>>>(conv_b + (size_t)l * H, N);
    }

    colsum_kernel<<<512, 128>>>(N);
    head_kernel<<<1, 128>>>(fc1_w, fc1_b, fc2_w, fc2_b, out, N);
}